// round 16
// baseline (speedup 1.0000x reference)
#include <cuda_runtime.h>
#include <math.h>
#include <stdint.h>

// ============================================================================
// HAWQ-style quantized 3-conv pipeline — all-f32 IEEE pipeline (round-7 base)
// with XLA's reciprocal-multiply rewrite at division-by-BROADCAST-scalar sites:
//   x_int  = round(x * frcp_rn(sf0))          (x / broadcast(sf))
//   w_int  = round(w * frcp_rn(w_sf[o]))      (w / broadcast(w_sf))
//   z      = scale_ch * frcp_rn(new_sf)       (scale_ch / broadcast(new_sf))
// True rn-division kept at non-broadcast sites: /127, /255, b/(act_sf*w_sf).
// Convs are exact int32 (order-independent; matches any backend).
// ============================================================================

#define BB 16

__device__ __align__(16) int8_t  g_Xs1[BB*32*32*320];   // stage-1 input, s8 NHWC
__device__ __align__(16) uint8_t g_Xu2[BB*32*32*192];   // stage-2 input, u8
__device__ __align__(16) uint8_t g_Xu3[BB*16*16*192];   // stage-3 input, u8
__device__ __align__(16) int8_t  g_W1[192*3*3*320];     // [o][kh][kw][c]
__device__ __align__(16) int8_t  g_W2[192*5*5*192];
__device__ __align__(16) int8_t  g_W3[192*5*5*192];
__device__ __align__(16) int     g_Y1[BB*32*32*192];    // post-bias+ReLU int32
__device__ __align__(16) int     g_Y2[BB*16*16*192];

__device__ float    g_wsf[3][192];
__device__ int      g_badd[3][192];
__device__ float    g_sc[2][192];               // act_sf*w_sf
__device__ float    g_rm[2][192], g_rs[2][192]; // requant m_int, exact 2^(e-31)
__device__ float    g_fm[192], g_fs[192];       // final dyadic
__device__ unsigned g_max[4];
__device__ float    g_par[4];                   // [0]=sf0, [1]=2^-ga, [2]=rcp(sf0)

// Exact 2^k for k in [-126, 127].
__device__ __forceinline__ float exact_exp2(int k) {
    return __int_as_float((k + 127) << 23);
}
// Exact frexp for positive normal floats: z = m * 2^e, m in [0.5, 1).
__device__ __forceinline__ float frexp_pos(float z, int* e) {
    unsigned b = __float_as_uint(z);
    *e = (int)(b >> 23) - 126;
    return __uint_as_float((b & 0x007FFFFFu) | 0x3F000000u);
}

// ---------------------------------------------------------------------------
__global__ void init_k() { if (threadIdx.x < 4) g_max[threadIdx.x] = 0u; }

__global__ void maxabs_k(const float* __restrict__ x, int n)
{
    float m = 0.f;
    for (int i = blockIdx.x * blockDim.x + threadIdx.x; i < n; i += gridDim.x * blockDim.x)
        m = fmaxf(m, fabsf(x[i]));
    #pragma unroll
    for (int off = 16; off; off >>= 1) m = fmaxf(m, __shfl_xor_sync(~0u, m, off));
    if ((threadIdx.x & 31) == 0) atomicMax(&g_max[0], __float_as_uint(m));
}

// ---------------------------------------------------------------------------
// Weight quant: w_sf = absmax/127 (true rn div); w_int = round(w * rcp(w_sf))
// — XLA reciprocal-multiply for the broadcast divide.
template <int STAGE>
__global__ void wquant_k(const float* __restrict__ w)
{
    constexpr int C  = (STAGE == 1) ? 320 : 192;
    constexpr int KH = (STAGE == 1) ? 3 : 5;
    constexpr int KW = KH;
    int8_t* wq = (STAGE == 1) ? g_W1 : ((STAGE == 2) ? g_W2 : g_W3);

    const int o = blockIdx.x;
    const int n = C * KH * KW;
    const float* wo = w + (long)o * n;

    __shared__ float rf[256];
    __shared__ float s_rcp;

    float mx = 0.f;
    for (int i = threadIdx.x; i < n; i += 256) mx = fmaxf(mx, fabsf(wo[i]));
    rf[threadIdx.x] = mx; __syncthreads();
    for (int s = 128; s; s >>= 1) {
        if (threadIdx.x < s) rf[threadIdx.x] = fmaxf(rf[threadIdx.x], rf[threadIdx.x + s]);
        __syncthreads();
    }
    if (threadIdx.x == 0) {
        float sf = __fdiv_rn(fmaxf(rf[0], 1e-8f), 127.0f);   // true div (constant)
        g_wsf[STAGE - 1][o] = sf;
        s_rcp = __frcp_rn(sf);                               // hoisted reciprocal
    }
    __syncthreads();
    const float rcp = s_rcp;

    for (int i = threadIdx.x; i < n; i += 256) {
        int kw_ = i % KW; int t = i / KW; int kh_ = t % KH; int c = t / KH;
        float q = rintf(wo[i] * rcp);                        // RECIP-MUL divide
        q = fminf(fmaxf(q, -128.f), 127.f);
        wq[((o * KH + kh_) * KW + kw_) * C + c] = (int8_t)(int)q;
    }
}

// ---------------------------------------------------------------------------
__global__ void p1_k(const float* __restrict__ b1, const int* __restrict__ ga)
{
    __shared__ float s_sf0;
    if (threadIdx.x == 0) {
        float inv = exact_exp2(-ga[0]);                 // x/2^ga: exact either way
        float mx  = __uint_as_float(g_max[0]) * inv;
        float sf0 = __fdiv_rn(fmaxf(mx, 1e-8f), 127.0f);  // true div (constant)
        g_par[0] = sf0; g_par[1] = inv;
        g_par[2] = __frcp_rn(sf0);                        // hoisted reciprocal
        s_sf0 = sf0;
    }
    __syncthreads();
    int o = threadIdx.x;
    if (o < 192) {
        float sc = s_sf0 * g_wsf[0][o];
        g_sc[0][o]   = sc;
        g_badd[0][o] = __float2int_rn(__fdiv_rn(b1[o], sc));  // vec/vec: true div
    }
}

template <int ST>   // ST = 2 or 3
__global__ void pN_k(const float* __restrict__ b)
{
    __shared__ float s_nsf, s_rcp;
    if (threadIdx.x == 0) {
        float nsf = __fdiv_rn(fmaxf(__uint_as_float(g_max[ST - 1]), 1e-8f), 255.0f);
        s_nsf = nsf;
        s_rcp = __frcp_rn(nsf);                          // hoisted reciprocal
    }
    __syncthreads();
    int o = threadIdx.x;
    if (o < 192) {
        float z = g_sc[ST - 2][o] * s_rcp;               // RECIP-MUL divide
        int e; float mm = frexp_pos(z, &e);
        g_rm[ST - 2][o] = rintf(mm * 2147483648.0f);     // exact (24-bit mantissa)
        g_rs[ST - 2][o] = exact_exp2(e - 31);            // exact 2^-(31-e)
        float scn = s_nsf * g_wsf[ST - 1][o];
        g_badd[ST - 1][o] = __float2int_rn(__fdiv_rn(b[o], scn)); // vec/vec: true div
        if (ST == 2) {
            g_sc[1][o] = scn;
        } else {
            int e2; float m2 = frexp_pos(scn, &e2);
            g_fm[o] = rintf(m2 * 2147483648.0f);
            g_fs[o] = exact_exp2(e2 - 31);
        }
    }
}

// ---------------------------------------------------------------------------
// Quantize x: round(x * rcp(sf0)) — reciprocal-multiply broadcast divide.
__global__ void quantx_k(const float* __restrict__ x)
{
    const int total = BB * 32 * 32 * 320;
    int idx = blockIdx.x * blockDim.x + threadIdx.x;
    if (idx >= total) return;
    int c = idx % 320; int t = idx / 320;
    int iw = t % 32; t /= 32;
    int ih = t % 32; int b = t / 32;
    float xx = x[((b * 320 + c) * 32 + ih) * 32 + iw] * g_par[1];  // exact /2^ga
    float q  = rintf(xx * g_par[2]);                               // RECIP-MUL
    q = fminf(fmaxf(q, -128.f), 127.f);
    g_Xs1[idx] = (int8_t)(int)q;
}

// Per-stage activation max (f32 products, same rounding as reference).
__global__ void gmax_k(int stage)
{
    const int* Y = (stage == 1) ? g_Y1 : g_Y2;
    const float* sc = g_sc[stage - 1];
    const int n = (stage == 1) ? BB * 32 * 32 * 192 : BB * 16 * 16 * 192;
    float m = 0.f;
    for (int i = blockIdx.x * blockDim.x + threadIdx.x; i < n; i += gridDim.x * blockDim.x)
        m = fmaxf(m, (float)Y[i] * sc[i % 192]);
    #pragma unroll
    for (int off = 16; off; off >>= 1) m = fmaxf(m, __shfl_xor_sync(~0u, m, off));
    if ((threadIdx.x & 31) == 0) atomicMax(&g_max[stage], __float_as_uint(m));
}

// Requant int32 -> u8: round((Y*m) * 2^(e-31)) — dyadic, exact either way.
template <int STAGE>
__global__ void requant_k()
{
    const int*  Y  = (STAGE == 1) ? g_Y1 : g_Y2;
    uint8_t*    Xu = (STAGE == 1) ? g_Xu2 : g_Xu3;
    const float* m = g_rm[STAGE - 1];
    const float* s = g_rs[STAGE - 1];
    const int total = (STAGE == 1) ? BB * 32 * 32 * 192 : BB * 16 * 16 * 192;
    int idx = blockIdx.x * blockDim.x + threadIdx.x;
    if (idx >= total) return;
    int c = idx % 192;
    float q = rintf(((float)Y[idx] * m[c]) * s[c]);
    q = fminf(fmaxf(q, 0.f), 255.f);
    Xu[idx] = (uint8_t)(int)q;
}

// ---------------------------------------------------------------------------
// Exact int32 convs.
template <int STAGE>
__global__ void sconv_k(float* __restrict__ outF)
{
    constexpr int C  = (STAGE == 1) ? 320 : 192;
    constexpr int KH = (STAGE == 1) ? 3 : 5;
    constexpr int S  = (STAGE == 1) ? 1 : 2;
    constexpr int P  = (STAGE == 1) ? 1 : 2;
    constexpr int HI = (STAGE == 3) ? 16 : 32;
    constexpr int HO = (STAGE == 1) ? 32 : ((STAGE == 2) ? 16 : 8);

    const int8_t* Wt = (STAGE == 1) ? g_W1 : ((STAGE == 2) ? g_W2 : g_W3);

    const int total = BB * HO * HO * 192;
    int t = blockIdx.x * blockDim.x + threadIdx.x;
    if (t >= total) return;
    int oc = t % 192; int p = t / 192;
    int ow = p % HO; int oh = (p / HO) % HO; int b = p / (HO * HO);

    int sum = 0;
    for (int kh = 0; kh < KH; kh++) {
        int ih = oh * S - P + kh;
        if ((unsigned)ih >= (unsigned)HI) continue;
        for (int kw = 0; kw < KH; kw++) {
            int iw = ow * S - P + kw;
            if ((unsigned)iw >= (unsigned)HI) continue;
            const int8_t* wrow = Wt + (oc * KH * KH + kh * KH + kw) * C;
            if (STAGE == 1) {
                const int8_t* xrow = g_Xs1 + ((b * HI + ih) * HI + iw) * C;
                #pragma unroll 4
                for (int c = 0; c < C; c += 4) {
                    char4 xa = *reinterpret_cast<const char4*>(xrow + c);
                    char4 wa = *reinterpret_cast<const char4*>(wrow + c);
                    sum += (int)xa.x * wa.x + (int)xa.y * wa.y
                         + (int)xa.z * wa.z + (int)xa.w * wa.w;
                }
            } else {
                const uint8_t* xrow = ((STAGE == 2) ? g_Xu2 : g_Xu3)
                                      + ((b * HI + ih) * HI + iw) * C;
                #pragma unroll 4
                for (int c = 0; c < C; c += 4) {
                    uchar4 xa = *reinterpret_cast<const uchar4*>(xrow + c);
                    char4  wa = *reinterpret_cast<const char4*>(wrow + c);
                    sum += (int)xa.x * wa.x + (int)xa.y * wa.y
                         + (int)xa.z * wa.z + (int)xa.w * wa.w;
                }
            }
        }
    }

    if (STAGE < 3) {
        int v = sum + g_badd[STAGE - 1][oc];
        v = v > 0 ? v : 0;
        ((STAGE == 1) ? g_Y1 : g_Y2)[t] = v;
    } else {
        int v = sum + g_badd[2][oc];
        outF[((b * 192 + oc) * HO + oh) * HO + ow] =
            rintf(((float)v * g_fm[oc]) * g_fs[oc]);
    }
}

// ---------------------------------------------------------------------------
extern "C" void kernel_launch(void* const* d_in, const int* in_sizes, int n_in,
                              void* d_out, int out_size)
{
    const float* x  = (const float*)d_in[0];
    const float* w1 = (const float*)d_in[1];
    const float* b1 = (const float*)d_in[2];
    const float* w2 = (const float*)d_in[3];
    const float* b2 = (const float*)d_in[4];
    const float* w3 = (const float*)d_in[5];
    const float* b3 = (const float*)d_in[6];
    const int*   ga = (const int*)d_in[7];
    float* out = (float*)d_out;

    const int nX  = BB * 320 * 32 * 32;
    const int n1o = BB * 32 * 32 * 192;
    const int n2o = BB * 16 * 16 * 192;
    const int n3o = BB * 8 * 8 * 192;

    init_k<<<1, 32>>>();
    maxabs_k<<<1024, 256>>>(x, nX);
    wquant_k<1><<<192, 256>>>(w1);
    wquant_k<2><<<192, 256>>>(w2);
    wquant_k<3><<<192, 256>>>(w3);
    p1_k<<<1, 192>>>(b1, ga);
    quantx_k<<<(nX + 255) / 256, 256>>>(x);

    sconv_k<1><<<(n1o + 255) / 256, 256>>>(nullptr);
    gmax_k<<<2048, 256>>>(1);
    pN_k<2><<<1, 192>>>(b2);
    requant_k<1><<<(n1o + 255) / 256, 256>>>();

    sconv_k<2><<<(n2o + 255) / 256, 256>>>(nullptr);
    gmax_k<<<512, 256>>>(2);
    pN_k<3><<<1, 192>>>(b3);
    requant_k<2><<<(n2o + 255) / 256, 256>>>();

    sconv_k<3><<<(n3o + 255) / 256, 256>>>(out);
}

// round 17
// speedup vs baseline: 5.7339x; 5.7339x over previous
#include <cuda_runtime.h>
#include <math.h>
#include <stdint.h>

// ============================================================================
// HAWQ-style quantized 3-conv pipeline — EXACT semantics frozen from round 16
// (XLA reciprocal-multiply at x-quant / w-quant / z sites; rest IEEE f32).
// Performance: tiled dp4a convs over padded NHWC buffers, fused max epilogue.
//   Stage 1: 3x3 s1 p1, 320->192, 32x32, s8 (halo 0)
//   Stage 2: 5x5 s2 p2, 192->192, ->16x16, u8-128 offset s8 (halo -128)
//   Stage 3: 5x5 s2 p2, 192->192, ->8x8,  u8-128 offset s8 (halo -128)
// Offset trick: true_conv = dp4a_conv + 128*sum(w) (folded into bias).
// ============================================================================

#define BB 16

__device__ __align__(16) int8_t  g_X1[BB*34*34*320];    // padded s8
__device__ __align__(16) int8_t  g_X2[BB*36*36*192];    // padded offset-s8
__device__ __align__(16) int8_t  g_X3[BB*20*20*192];    // padded offset-s8
__device__ __align__(16) int8_t  g_W1[192*3*3*320];     // [o][kh][kw][c]
__device__ __align__(16) int8_t  g_W2[192*5*5*192];
__device__ __align__(16) int8_t  g_W3[192*5*5*192];
__device__ __align__(16) int     g_Y1[BB*32*32*192];    // [pixel][oc] post-bias+ReLU
__device__ __align__(16) int     g_Y2[BB*16*16*192];

__device__ float    g_wsf[3][192];
__device__ int      g_wsum[3][192];
__device__ int      g_badd[3][192];   // bias (+128*wsum for stages 2,3)
__device__ float    g_sc[2][192];
__device__ float    g_rm[2][192], g_rs[2][192]; // requant m_int, exact 2^(e-31)
__device__ float    g_fm[192], g_fs[192];       // final dyadic
__device__ unsigned g_max[4];
__device__ float    g_par[4];                   // [0]=sf0, [1]=2^-ga, [2]=rcp(sf0)

// Exact 2^k for k in [-126, 127].
__device__ __forceinline__ float exact_exp2(int k) {
    return __int_as_float((k + 127) << 23);
}
// Exact frexp for positive normal floats.
__device__ __forceinline__ float frexp_pos(float z, int* e) {
    unsigned b = __float_as_uint(z);
    *e = (int)(b >> 23) - 126;
    return __uint_as_float((b & 0x007FFFFFu) | 0x3F000000u);
}

// ---------------------------------------------------------------------------
__global__ void init_k() { if (threadIdx.x < 4) g_max[threadIdx.x] = 0u; }

// Initialize padded buffers: X1 = 0, X2/X3 = 0x80 (-128). int4 stores.
__global__ void clear_k()
{
    const int n1 = BB*34*34*320/16, n2 = BB*36*36*192/16, n3 = BB*20*20*192/16;
    int i = blockIdx.x * blockDim.x + threadIdx.x;
    int4 z = make_int4(0,0,0,0);
    int m = (int)0x80808080;
    int4 h = make_int4(m,m,m,m);
    if (i < n1) reinterpret_cast<int4*>(g_X1)[i] = z;
    if (i < n2) reinterpret_cast<int4*>(g_X2)[i] = h;
    if (i < n3) reinterpret_cast<int4*>(g_X3)[i] = h;
}

__global__ void maxabs_k(const float4* __restrict__ x, int n4)
{
    float m = 0.f;
    for (int i = blockIdx.x * blockDim.x + threadIdx.x; i < n4; i += gridDim.x * blockDim.x) {
        float4 v = x[i];
        m = fmaxf(m, fmaxf(fmaxf(fabsf(v.x), fabsf(v.y)), fmaxf(fabsf(v.z), fabsf(v.w))));
    }
    #pragma unroll
    for (int off = 16; off; off >>= 1) m = fmaxf(m, __shfl_xor_sync(~0u, m, off));
    if ((threadIdx.x & 31) == 0) atomicMax(&g_max[0], __float_as_uint(m));
}

// ---------------------------------------------------------------------------
// Weight quant: w_sf = absmax/127 (true div); w_int = round(w * frcp_rn(w_sf))
// (XLA reciprocal-multiply). Also integer sum of quantized weights.
template <int STAGE>
__global__ void wquant_k(const float* __restrict__ w)
{
    constexpr int C  = (STAGE == 1) ? 320 : 192;
    constexpr int KH = (STAGE == 1) ? 3 : 5;
    constexpr int KW = KH;
    int8_t* wq = (STAGE == 1) ? g_W1 : ((STAGE == 2) ? g_W2 : g_W3);

    const int o = blockIdx.x;
    const int n = C * KH * KW;
    const float* wo = w + (long)o * n;

    __shared__ float rf[256];
    __shared__ int   ri[256];
    __shared__ float s_rcp;

    float mx = 0.f;
    for (int i = threadIdx.x; i < n; i += 256) mx = fmaxf(mx, fabsf(wo[i]));
    rf[threadIdx.x] = mx; __syncthreads();
    for (int s = 128; s; s >>= 1) {
        if (threadIdx.x < s) rf[threadIdx.x] = fmaxf(rf[threadIdx.x], rf[threadIdx.x + s]);
        __syncthreads();
    }
    if (threadIdx.x == 0) {
        float sf = __fdiv_rn(fmaxf(rf[0], 1e-8f), 127.0f);   // true div
        g_wsf[STAGE - 1][o] = sf;
        s_rcp = __frcp_rn(sf);                               // hoisted reciprocal
    }
    __syncthreads();
    const float rcp = s_rcp;

    int sum = 0;
    for (int i = threadIdx.x; i < n; i += 256) {
        int kw_ = i % KW; int t = i / KW; int kh_ = t % KH; int c = t / KH;
        float q = rintf(wo[i] * rcp);                        // RECIP-MUL divide
        q = fminf(fmaxf(q, -128.f), 127.f);
        int qi = (int)q;
        wq[((o * KH + kh_) * KW + kw_) * C + c] = (int8_t)qi;
        sum += qi;
    }
    ri[threadIdx.x] = sum; __syncthreads();
    for (int s = 128; s; s >>= 1) {
        if (threadIdx.x < s) ri[threadIdx.x] += ri[threadIdx.x + s];
        __syncthreads();
    }
    if (threadIdx.x == 0) g_wsum[STAGE - 1][o] = ri[0];
}

// ---------------------------------------------------------------------------
__global__ void p1_k(const float* __restrict__ b1, const int* __restrict__ ga)
{
    __shared__ float s_sf0;
    if (threadIdx.x == 0) {
        float inv = exact_exp2(-ga[0]);
        float mx  = __uint_as_float(g_max[0]) * inv;
        float sf0 = __fdiv_rn(fmaxf(mx, 1e-8f), 127.0f);     // true div
        g_par[0] = sf0; g_par[1] = inv;
        g_par[2] = __frcp_rn(sf0);                           // hoisted reciprocal
        s_sf0 = sf0;
    }
    __syncthreads();
    int o = threadIdx.x;
    if (o < 192) {
        float sc = s_sf0 * g_wsf[0][o];
        g_sc[0][o]   = sc;
        g_badd[0][o] = __float2int_rn(__fdiv_rn(b1[o], sc)); // vec/vec true div
    }
}

template <int ST>   // ST = 2 or 3
__global__ void pN_k(const float* __restrict__ b)
{
    __shared__ float s_nsf, s_rcp;
    if (threadIdx.x == 0) {
        float nsf = __fdiv_rn(fmaxf(__uint_as_float(g_max[ST - 1]), 1e-8f), 255.0f);
        s_nsf = nsf;
        s_rcp = __frcp_rn(nsf);                              // hoisted reciprocal
    }
    __syncthreads();
    int o = threadIdx.x;
    if (o < 192) {
        float z = g_sc[ST - 2][o] * s_rcp;                   // RECIP-MUL divide
        int e; float mm = frexp_pos(z, &e);
        g_rm[ST - 2][o] = rintf(mm * 2147483648.0f);
        g_rs[ST - 2][o] = exact_exp2(e - 31);
        float scn = s_nsf * g_wsf[ST - 1][o];
        int bi = __float2int_rn(__fdiv_rn(b[o], scn));       // vec/vec true div
        g_badd[ST - 1][o] = bi + 128 * g_wsum[ST - 1][o];    // offset-trick fold
        if (ST == 2) {
            g_sc[1][o] = scn;
        } else {
            int e2; float m2 = frexp_pos(scn, &e2);
            g_fm[o] = rintf(m2 * 2147483648.0f);
            g_fs[o] = exact_exp2(e2 - 31);
        }
    }
}

// ---------------------------------------------------------------------------
// Quantize x NCHW -> padded NHWC s8 via 32x32 smem transpose tiles.
// grid (32, 10, 16), block (32, 8).
__global__ void quantx_k(const float* __restrict__ x)
{
    __shared__ float tile[32][33];
    const int p0 = blockIdx.x * 32;       // pixel base (h*32+w within image)
    const int c0 = blockIdx.y * 32;       // channel base
    const int b  = blockIdx.z;

    #pragma unroll
    for (int r = threadIdx.y; r < 32; r += 8)
        tile[r][threadIdx.x] = x[((b * 320 + c0 + r) * 1024) + p0 + threadIdx.x];
    __syncthreads();

    const float inv = g_par[1], rcp = g_par[2];
    #pragma unroll
    for (int r = threadIdx.y; r < 32; r += 8) {
        int p  = p0 + r;
        int ih = p >> 5, iw = p & 31;
        float v = tile[threadIdx.x][r] * inv;        // exact /2^ga
        float q = rintf(v * rcp);                    // RECIP-MUL divide
        q = fminf(fmaxf(q, -128.f), 127.f);
        g_X1[((b * 34 + ih + 1) * 34 + iw + 1) * 320 + c0 + threadIdx.x] =
            (int8_t)(int)q;
    }
}

// Requant int32 -> offset-s8 into padded buffer (interior only; halo preset).
template <int STAGE>
__global__ void requant_k()
{
    constexpr int OH  = (STAGE == 1) ? 32 : 16;
    constexpr int IHP = (STAGE == 1) ? 36 : 20;
    const int*  Y  = (STAGE == 1) ? g_Y1 : g_Y2;
    int8_t*     Xq = (STAGE == 1) ? g_X2 : g_X3;
    const float* m = g_rm[STAGE - 1];
    const float* s = g_rs[STAGE - 1];
    const int total = BB * OH * OH * 192;
    int idx = blockIdx.x * blockDim.x + threadIdx.x;
    if (idx >= total) return;
    int c = idx % 192; int p = idx / 192;
    int ow = p % OH; int oh = (p / OH) % OH; int b = p / (OH * OH);
    float q = rintf(((float)Y[idx] * m[c]) * s[c]);
    q = fminf(fmaxf(q, 0.f), 255.f);
    Xq[((b * IHP + oh + 2) * IHP + ow + 2) * 192 + c] = (int8_t)((int)q - 128);
}

// ---------------------------------------------------------------------------
// Tiled dp4a conv: 64 output pixels x 64 output channels per 256-thread block.
// K in 64-channel chunks through transposed smem [kword][row].
// Fused epilogue: bias + ReLU + store Y + atomicMax of f32-scaled activations
// (stages 1,2) or final dyadic dequant to NCHW f32 (stage 3).
template <int STAGE>
__global__ __launch_bounds__(256) void conv_k(float* __restrict__ outF)
{
    constexpr int C   = (STAGE == 1) ? 320 : 192;
    constexpr int KH  = (STAGE == 1) ? 3 : 5;
    constexpr int KW  = KH;
    constexpr int S   = (STAGE == 1) ? 1 : 2;
    constexpr int IH  = (STAGE == 1) ? 34 : ((STAGE == 2) ? 36 : 20);
    constexpr int IW  = IH;
    constexpr int OH  = (STAGE == 1) ? 32 : ((STAGE == 2) ? 16 : 8);
    constexpr int OW  = OH;
    constexpr int NCH = C / 64;

    const int8_t* X = (STAGE == 1) ? g_X1 : ((STAGE == 2) ? g_X2 : g_X3);
    const int8_t* W = (STAGE == 1) ? g_W1 : ((STAGE == 2) ? g_W2 : g_W3);

    __shared__ __align__(16) int XS[16][68];
    __shared__ __align__(16) int WS[16][68];
    __shared__ int pixb[64];

    const int tid = threadIdx.x;
    const int pi  = tid & 15;     // pixel-group index (4 pixels each)
    const int oi  = tid >> 4;     // och-group index   (4 channels each)
    const int pxbase = blockIdx.x * 64;
    const int ocbase = blockIdx.y * 64;

    if (tid < 64) {
        int p = pxbase + tid;
        int b = p / (OH * OW); int r = p - b * (OH * OW);
        int oh = r / OW, ow = r - oh * OW;
        pixb[tid] = ((b * IH + oh * S) * IW + ow * S) * C;
    }
    __syncthreads();

    const int lpx = tid >> 2, lpart = tid & 3;
    const int8_t* xptr0 = X + pixb[lpx] + lpart * 16;
    const int8_t* wrb   = W + (ocbase + lpx) * (KH * KW * C) + lpart * 16;

    int acc[4][4] = {};

    for (int kp = 0; kp < KH * KW; kp++) {
        const int kh = kp / KW, kw = kp - kh * KW;
        const int8_t* xk = xptr0 + (kh * IW + kw) * C;
        const int8_t* wk = wrb + kp * C;
        #pragma unroll
        for (int cc = 0; cc < NCH; cc++) {
            int4 xv = *reinterpret_cast<const int4*>(xk + cc * 64);
            int4 wv = *reinterpret_cast<const int4*>(wk + cc * 64);
            XS[lpart * 4 + 0][lpx] = xv.x; XS[lpart * 4 + 1][lpx] = xv.y;
            XS[lpart * 4 + 2][lpx] = xv.z; XS[lpart * 4 + 3][lpx] = xv.w;
            WS[lpart * 4 + 0][lpx] = wv.x; WS[lpart * 4 + 1][lpx] = wv.y;
            WS[lpart * 4 + 2][lpx] = wv.z; WS[lpart * 4 + 3][lpx] = wv.w;
            __syncthreads();
            #pragma unroll
            for (int j = 0; j < 16; j++) {
                int4 a  = *reinterpret_cast<const int4*>(&XS[j][pi * 4]);
                int4 w4 = *reinterpret_cast<const int4*>(&WS[j][oi * 4]);
                int av[4]  = {a.x, a.y, a.z, a.w};
                int wv4[4] = {w4.x, w4.y, w4.z, w4.w};
                #pragma unroll
                for (int p = 0; p < 4; p++)
                    #pragma unroll
                    for (int o = 0; o < 4; o++)
                        acc[p][o] = __dp4a(av[p], wv4[o], acc[p][o]);
            }
            __syncthreads();
        }
    }

    const int pxi = pxbase + pi * 4;
    if (STAGE < 3) {
        int* Y = (STAGE == 1) ? g_Y1 : g_Y2;
        const int*   bd = g_badd[STAGE - 1];
        const float* sc = g_sc[STAGE - 1];
        float lm = 0.f;
        #pragma unroll
        for (int p = 0; p < 4; p++) {
            #pragma unroll
            for (int o = 0; o < 4; o++) {
                int oc = ocbase + oi * 4 + o;
                int v = acc[p][o] + bd[oc];
                v = v > 0 ? v : 0;
                Y[(pxi + p) * 192 + oc] = v;
                lm = fmaxf(lm, (float)v * sc[oc]);   // same f32 product as ref max
            }
        }
        #pragma unroll
        for (int off = 16; off; off >>= 1) lm = fmaxf(lm, __shfl_xor_sync(~0u, lm, off));
        if ((tid & 31) == 0) atomicMax(&g_max[STAGE], __float_as_uint(lm));
    } else {
        #pragma unroll
        for (int p = 0; p < 4; p++) {
            int px = pxi + p;
            int b = px / (OH * OW); int r = px - b * (OH * OW);
            int oh = r / OW, ow = r - oh * OW;
            #pragma unroll
            for (int o = 0; o < 4; o++) {
                int oc = ocbase + oi * 4 + o;
                int v = acc[p][o] + g_badd[2][oc];
                outF[((b * 192 + oc) * OH + oh) * OW + ow] =
                    rintf(((float)v * g_fm[oc]) * g_fs[oc]);
            }
        }
    }
}

// ---------------------------------------------------------------------------
extern "C" void kernel_launch(void* const* d_in, const int* in_sizes, int n_in,
                              void* d_out, int out_size)
{
    const float* x  = (const float*)d_in[0];
    const float* w1 = (const float*)d_in[1];
    const float* b1 = (const float*)d_in[2];
    const float* w2 = (const float*)d_in[3];
    const float* b2 = (const float*)d_in[4];
    const float* w3 = (const float*)d_in[5];
    const float* b3 = (const float*)d_in[6];
    const int*   ga = (const int*)d_in[7];
    float* out = (float*)d_out;

    const int nX  = BB * 320 * 32 * 32;
    const int n1o = BB * 32 * 32 * 192;
    const int n2o = BB * 16 * 16 * 192;
    const int nclr = BB * 34 * 34 * 320 / 16;   // largest /16

    init_k<<<1, 32>>>();
    clear_k<<<(nclr + 255) / 256, 256>>>();
    maxabs_k<<<1024, 256>>>((const float4*)x, nX / 4);
    wquant_k<1><<<192, 256>>>(w1);
    wquant_k<2><<<192, 256>>>(w2);
    wquant_k<3><<<192, 256>>>(w3);
    p1_k<<<1, 192>>>(b1, ga);
    quantx_k<<<dim3(32, 10, BB), dim3(32, 8)>>>(x);

    conv_k<1><<<dim3(256, 3), 256>>>(nullptr);
    pN_k<2><<<1, 192>>>(b2);
    requant_k<1><<<(n1o + 255) / 256, 256>>>();

    conv_k<2><<<dim3(64, 3), 256>>>(nullptr);
    pN_k<3><<<1, 192>>>(b3);
    requant_k<2><<<(n2o + 255) / 256, 256>>>();

    conv_k<3><<<dim3(16, 3), 256>>>(out);
}